// round 2
// baseline (speedup 1.0000x reference)
#include <cuda_runtime.h>

#define GN        128
#define GMASK     127
#define NCELLS    (GN * GN * GN)        // 2,097,152
#define NPTS_MAX  1000000

#define SCAN_TPB          256
#define SCAN_ITEMS        4
#define SCAN_BLOCK_ITEMS  (SCAN_TPB * SCAN_ITEMS)   // 1024
#define SCAN_NBLK         (NCELLS / SCAN_BLOCK_ITEMS) // 2048

// ---- scratch (static device arrays; no allocation allowed) ----
__device__ unsigned g_counts[NCELLS];            // 8 MB  (destroyed by scatter)
__device__ unsigned g_cellStart[NCELLS + 1];     // 8 MB
__device__ unsigned g_partials[SCAN_NBLK];       // 8 KB
__device__ float4   g_possorted[NPTS_MAX];       // 16 MB  {relx, rely, relz, bitcast(orig idx)}
__device__ float4   g_featsorted[NPTS_MAX * 2];  // 32 MB
__device__ float4   g_grid[NCELLS * 2];          // 64 MB  [cell][8 f32]

// ---------------- histogram ----------------
__global__ __launch_bounds__(256)
void hist_kernel(const float* __restrict__ pos, int n) {
    int i = blockIdx.x * blockDim.x + threadIdx.x;
    if (i >= n) return;
    float rx = pos[3 * i + 0] * (float)GN;
    float ry = pos[3 * i + 1] * (float)GN;
    float rz = pos[3 * i + 2] * (float)GN;
    int cid = (((int)rx) << 14) | (((int)ry) << 7) | ((int)rz);
    atomicAdd(&g_counts[cid], 1u);
}

// ---------------- scan helpers ----------------
__device__ __forceinline__ unsigned blk_excl_scan_256(unsigned v, unsigned* swarp) {
    int lane = threadIdx.x & 31, wid = threadIdx.x >> 5;
    unsigned inc = v;
    #pragma unroll
    for (int o = 1; o < 32; o <<= 1) {
        unsigned t = __shfl_up_sync(0xffffffffu, inc, o);
        if (lane >= o) inc += t;
    }
    if (lane == 31) swarp[wid] = inc;
    __syncthreads();
    if (wid == 0) {
        unsigned w = (lane < 8) ? swarp[lane] : 0;
        #pragma unroll
        for (int o = 1; o < 8; o <<= 1) {
            unsigned t = __shfl_up_sync(0xffffffffu, w, o);
            if (lane >= o) w += t;
        }
        if (lane < 8) swarp[lane] = w;   // inclusive scan of warp sums
    }
    __syncthreads();
    unsigned warp_off = wid ? swarp[wid - 1] : 0;
    return warp_off + inc - v;           // exclusive prefix
}

__global__ __launch_bounds__(SCAN_TPB)
void scan_partials_kernel() {
    __shared__ unsigned ssum[8];
    int base = blockIdx.x * SCAN_BLOCK_ITEMS + threadIdx.x * SCAN_ITEMS;
    unsigned s = 0;
    #pragma unroll
    for (int k = 0; k < SCAN_ITEMS; k++) s += g_counts[base + k];
    #pragma unroll
    for (int o = 16; o; o >>= 1) s += __shfl_down_sync(0xffffffffu, s, o);
    if ((threadIdx.x & 31) == 0) ssum[threadIdx.x >> 5] = s;
    __syncthreads();
    if (threadIdx.x == 0) {
        unsigned t = 0;
        #pragma unroll
        for (int w = 0; w < 8; w++) t += ssum[w];
        g_partials[blockIdx.x] = t;
    }
}

__global__ __launch_bounds__(SCAN_TPB)
void scan_top_kernel(int n) {
    __shared__ unsigned swarp[8];
    unsigned v[8];
    int base = threadIdx.x * 8;        // 256 * 8 = 2048 partials
    unsigned local = 0;
    #pragma unroll
    for (int k = 0; k < 8; k++) { v[k] = g_partials[base + k]; local += v[k]; }
    unsigned excl = blk_excl_scan_256(local, swarp);
    unsigned run = excl;
    #pragma unroll
    for (int k = 0; k < 8; k++) { unsigned t = v[k]; g_partials[base + k] = run; run += t; }
    if (threadIdx.x == 0) g_cellStart[NCELLS] = (unsigned)n;
}

__global__ __launch_bounds__(SCAN_TPB)
void scan_low_kernel() {
    __shared__ unsigned swarp[8];
    int base = blockIdx.x * SCAN_BLOCK_ITEMS + threadIdx.x * SCAN_ITEMS;
    unsigned v[SCAN_ITEMS];
    unsigned local = 0;
    #pragma unroll
    for (int k = 0; k < SCAN_ITEMS; k++) { v[k] = g_counts[base + k]; local += v[k]; }
    unsigned excl = blk_excl_scan_256(local, swarp);
    unsigned off = g_partials[blockIdx.x] + excl;
    #pragma unroll
    for (int k = 0; k < SCAN_ITEMS; k++) { g_cellStart[base + k] = off; off += v[k]; }
}

// ---------------- scatter (reorder points into cell order) ----------------
__global__ __launch_bounds__(256)
void scatter_kernel(const float* __restrict__ pos,
                    const float4* __restrict__ feat4, int n) {
    int i = blockIdx.x * blockDim.x + threadIdx.x;
    if (i >= n) return;
    float rx = pos[3 * i + 0] * (float)GN;
    float ry = pos[3 * i + 1] * (float)GN;
    float rz = pos[3 * i + 2] * (float)GN;
    int cid = (((int)rx) << 14) | (((int)ry) << 7) | ((int)rz);
    unsigned k = atomicSub(&g_counts[cid], 1u);       // returns old count
    unsigned dst = g_cellStart[cid] + k - 1;
    g_possorted[dst] = make_float4(rx, ry, rz, __int_as_float(i));
    g_featsorted[2 * dst + 0] = feat4[2 * i + 0];
    g_featsorted[2 * dst + 1] = feat4[2 * i + 1];
}

// ---------------- P2G as gather: one thread per grid node, no atomics ----------------
__global__ __launch_bounds__(256)
void p2g_gather_kernel() {
    int nid = blockIdx.x * blockDim.x + threadIdx.x;
    if (nid >= NCELLS) return;
    int nx = nid >> 14, ny = (nid >> 7) & GMASK, nz = nid & GMASK;

    float a0 = 0.f, a1 = 0.f, a2 = 0.f, a3 = 0.f;
    float a4 = 0.f, a5 = 0.f, a6 = 0.f, a7 = 0.f;

    #pragma unroll
    for (int ox = 0; ox < 2; ox++) {
        int bx = (nx - ox) & GMASK;
        #pragma unroll
        for (int oy = 0; oy < 2; oy++) {
            int by = (ny - oy) & GMASK;
            #pragma unroll
            for (int oz = 0; oz < 2; oz++) {
                int bz = (nz - oz) & GMASK;
                int cid = (bx << 14) | (by << 7) | bz;
                unsigned s = __ldg(&g_cellStart[cid]);
                unsigned e = __ldg(&g_cellStart[cid + 1]);
                for (unsigned p = s; p < e; p++) {
                    float4 pp = __ldg(&g_possorted[p]);
                    float fx = pp.x - (float)bx;
                    float fy = pp.y - (float)by;
                    float fz = pp.z - (float)bz;
                    float wx = ox ? fx : 1.f - fx;
                    float wy = oy ? fy : 1.f - fy;
                    float wz = oz ? fz : 1.f - fz;
                    float w = wx * wy * wz;
                    float4 f0 = __ldg(&g_featsorted[2 * p + 0]);
                    float4 f1 = __ldg(&g_featsorted[2 * p + 1]);
                    a0 += w * f0.x; a1 += w * f0.y; a2 += w * f0.z; a3 += w * f0.w;
                    a4 += w * f1.x; a5 += w * f1.y; a6 += w * f1.z; a7 += w * f1.w;
                }
            }
        }
    }
    g_grid[2 * nid + 0] = make_float4(a0, a1, a2, a3);
    g_grid[2 * nid + 1] = make_float4(a4, a5, a6, a7);
}

// ---------------- G2P over sorted points (cache-local gathers) ----------------
__global__ __launch_bounds__(256)
void g2p_sorted_kernel(float4* __restrict__ out4, int n) {
    int i = blockIdx.x * blockDim.x + threadIdx.x;
    if (i >= n) return;
    float4 pp = g_possorted[i];
    int bx = (int)pp.x, by = (int)pp.y, bz = (int)pp.z;
    float fx = pp.x - (float)bx, fy = pp.y - (float)by, fz = pp.z - (float)bz;

    float wxa[2] = {1.f - fx, fx};
    float wya[2] = {1.f - fy, fy};
    float wza[2] = {1.f - fz, fz};

    float4 acc0 = make_float4(0.f, 0.f, 0.f, 0.f);
    float4 acc1 = make_float4(0.f, 0.f, 0.f, 0.f);

    #pragma unroll
    for (int ox = 0; ox < 2; ox++) {
        int nx = (bx + ox) & GMASK;
        #pragma unroll
        for (int oy = 0; oy < 2; oy++) {
            int ny = (by + oy) & GMASK;
            float wxy = wxa[ox] * wya[oy];
            #pragma unroll
            for (int oz = 0; oz < 2; oz++) {
                int nz = (bz + oz) & GMASK;
                float w = wxy * wza[oz];
                int hid = (nx << 14) | (ny << 7) | nz;
                float4 g0 = __ldg(&g_grid[2 * hid + 0]);
                float4 g1 = __ldg(&g_grid[2 * hid + 1]);
                acc0.x += w * g0.x; acc0.y += w * g0.y;
                acc0.z += w * g0.z; acc0.w += w * g0.w;
                acc1.x += w * g1.x; acc1.y += w * g1.y;
                acc1.z += w * g1.z; acc1.w += w * g1.w;
            }
        }
    }
    int orig = __float_as_int(pp.w);
    out4[2 * orig + 0] = acc0;
    out4[2 * orig + 1] = acc1;
}

extern "C" void kernel_launch(void* const* d_in, const int* in_sizes, int n_in,
                              void* d_out, int out_size) {
    const float* pos  = (const float*)d_in[0];   // [N,3] f32
    const float* feat = (const float*)d_in[1];   // [N,8] f32
    float* out        = (float*)d_out;           // [N,8] f32
    int n = in_sizes[0] / 3;

    void* cptr = nullptr;
    cudaGetSymbolAddress(&cptr, g_counts);
    cudaMemsetAsync(cptr, 0, (size_t)NCELLS * sizeof(unsigned), 0);

    int tpb = 256;
    int pblocks = (n + tpb - 1) / tpb;

    hist_kernel<<<pblocks, tpb>>>(pos, n);
    scan_partials_kernel<<<SCAN_NBLK, SCAN_TPB>>>();
    scan_top_kernel<<<1, SCAN_TPB>>>(n);
    scan_low_kernel<<<SCAN_NBLK, SCAN_TPB>>>();
    scatter_kernel<<<pblocks, tpb>>>(pos, (const float4*)feat, n);
    p2g_gather_kernel<<<NCELLS / tpb, tpb>>>();
    g2p_sorted_kernel<<<pblocks, tpb>>>((float4*)out, n);
}